// round 6
// baseline (speedup 1.0000x reference)
#include <cuda_runtime.h>
#include <cstdint>

// Problem constants
constexpr int BB = 32;       // batch
constexpr int TT = 2048;     // time steps

// ---------------- scratch (static device globals; no allocation allowed) ----
__device__ float g_xg[(size_t)BB * TT * 3072];     // input-gate projections, max 3H=3072
__device__ float g_act0[(size_t)BB * TT * 1024];   // activation ping
__device__ float g_act1[(size_t)BB * TT * 1024];   // activation pong
__device__ float g_h[2 * 32 * 1024];               // hidden state, double buffered, layout f4[k>>2][b][k&3]
__device__ unsigned g_gen;                          // barrier generation (monotonic across launches)
__device__ unsigned g_flag[147 * 32];               // per-CTA arrival flags, 128B-strided

// ---------------- packed f32x2 helpers (sm_100+) ---------------------------
__device__ __forceinline__ void fma2(unsigned long long& a, unsigned long long x, unsigned long long y) {
    asm("fma.rn.f32x2 %0, %1, %2, %0;" : "+l"(a) : "l"(x), "l"(y));
}
__device__ __forceinline__ unsigned long long pk2(float x, float y) {
    unsigned long long r; asm("mov.b64 %0, {%1,%2};" : "=l"(r) : "f"(x), "f"(y)); return r;
}
__device__ __forceinline__ float2 up2(unsigned long long v) {
    float2 f; asm("mov.b64 {%0,%1}, %2;" : "=f"(f.x), "=f"(f.y) : "l"(v)); return f;
}

union HU { float4 f; ulonglong2 u; };

__device__ __forceinline__ void cpa16(void* dst, const void* src) {
    uint32_t d = (uint32_t)__cvta_generic_to_shared(dst);
    asm volatile("cp.async.cg.shared.global [%0], [%1], 16;" :: "r"(d), "l"(src));
}

__device__ __forceinline__ void st_rel(unsigned* p, unsigned v) {
    asm volatile("st.release.gpu.global.u32 [%0], %1;" :: "l"(p), "r"(v) : "memory");
}
__device__ __forceinline__ unsigned ld_acq(const unsigned* p) {
    unsigned v;
    asm volatile("ld.acquire.gpu.global.u32 %0, [%1];" : "=r"(v) : "l"(p) : "memory");
    return v;
}

// ---------------- input projection GEMM -------------------------------------
// C[m, n] = sum_k A[m, k] * W[n, k] + bias[n],  m = b*TT + t
// Tile: BM=128, BN=128, BK=16; 256 threads; 8x8 per thread via f32x2 row pairs.
// Register-staged pipelining: LDG next K-block while computing current tile.
__global__ __launch_bounds__(256, 2) void gemm_xg(
    const float* __restrict__ A, const float* __restrict__ W,
    const float* __restrict__ bias, float* __restrict__ C,
    int K, int N3, long sb, long st, long sk)
{
    __shared__ __align__(16) float As[16][128];
    __shared__ __align__(16) float Bs[16][128];

    int tid = threadIdx.x;
    int n0 = blockIdx.x * 128;
    int m0 = blockIdx.y * 128;
    int bidx = m0 / TT;
    int t0 = m0 % TT;          // TT % 128 == 0 so tile stays within one batch row
    const float* Ab = A + (size_t)bidx * sb + (size_t)t0 * st;
    int tx = tid & 15, ty = tid >> 4;

    unsigned long long acc[4][8];
#pragma unroll
    for (int p = 0; p < 4; ++p)
#pragma unroll
        for (int j = 0; j < 8; ++j) acc[p][j] = 0ull;

    float4 ra[2], rb[2];

    auto load_regs = [&](int k0) {
        if (sk == 1) {
#pragma unroll
            for (int i = 0; i < 2; ++i) {
                int lin = tid + i * 256;
                int m = lin >> 2, kq = (lin & 3) * 4;
                ra[i] = *(const float4*)(Ab + (size_t)m * st + (k0 + kq));
            }
        } else {
#pragma unroll
            for (int i = 0; i < 2; ++i) {
                int lin = tid + i * 256;
                int k = lin >> 5, m4 = (lin & 31) * 4;
                ra[i] = *(const float4*)(Ab + m4 + (size_t)(k0 + k) * sk);
            }
        }
#pragma unroll
        for (int i = 0; i < 2; ++i) {
            int lin = tid + i * 256;
            int n = lin >> 2, kq = (lin & 3) * 4;
            rb[i] = *(const float4*)&W[(size_t)(n0 + n) * K + k0 + kq];
        }
    };

    auto store_smem = [&]() {
        if (sk == 1) {
#pragma unroll
            for (int i = 0; i < 2; ++i) {
                int lin = tid + i * 256;
                int m = lin >> 2, kq = (lin & 3) * 4;
                As[kq + 0][m] = ra[i].x; As[kq + 1][m] = ra[i].y;
                As[kq + 2][m] = ra[i].z; As[kq + 3][m] = ra[i].w;
            }
        } else {
#pragma unroll
            for (int i = 0; i < 2; ++i) {
                int lin = tid + i * 256;
                int k = lin >> 5, m4 = (lin & 31) * 4;
                *(float4*)&As[k][m4] = ra[i];
            }
        }
#pragma unroll
        for (int i = 0; i < 2; ++i) {
            int lin = tid + i * 256;
            int n = lin >> 2, kq = (lin & 3) * 4;
            Bs[kq + 0][n] = rb[i].x; Bs[kq + 1][n] = rb[i].y;
            Bs[kq + 2][n] = rb[i].z; Bs[kq + 3][n] = rb[i].w;
        }
    };

    load_regs(0);
    store_smem();
    __syncthreads();

    for (int k0 = 0; k0 < K; k0 += 16) {
        bool last = (k0 + 16 >= K);
        if (!last) load_regs(k0 + 16);

#pragma unroll
        for (int k = 0; k < 16; ++k) {
            const ulonglong2* ap = (const ulonglong2*)&As[k][ty * 8];
            ulonglong2 A0 = ap[0], A1 = ap[1];
            unsigned long long am[4] = {A0.x, A0.y, A1.x, A1.y};
            float4 b0 = *(const float4*)&Bs[k][tx * 8];
            float4 b1 = *(const float4*)&Bs[k][tx * 8 + 4];
            unsigned long long bd[8] = {pk2(b0.x, b0.x), pk2(b0.y, b0.y),
                                        pk2(b0.z, b0.z), pk2(b0.w, b0.w),
                                        pk2(b1.x, b1.x), pk2(b1.y, b1.y),
                                        pk2(b1.z, b1.z), pk2(b1.w, b1.w)};
#pragma unroll
            for (int p = 0; p < 4; ++p)
#pragma unroll
                for (int j = 0; j < 8; ++j) fma2(acc[p][j], am[p], bd[j]);
        }
        __syncthreads();
        if (!last) {
            store_smem();
            __syncthreads();
        }
    }

    float4 bv0 = *(const float4*)&bias[n0 + tx * 8];
    float4 bv1 = *(const float4*)&bias[n0 + tx * 8 + 4];
#pragma unroll
    for (int p = 0; p < 4; ++p) {
        float2 c[8];
#pragma unroll
        for (int j = 0; j < 8; ++j) c[j] = up2(acc[p][j]);
        size_t r0 = (size_t)(m0 + ty * 8 + 2 * p) * N3 + n0 + tx * 8;
        float4 lo0 = {c[0].x + bv0.x, c[1].x + bv0.y, c[2].x + bv0.z, c[3].x + bv0.w};
        float4 hi0 = {c[4].x + bv1.x, c[5].x + bv1.y, c[6].x + bv1.z, c[7].x + bv1.w};
        float4 lo1 = {c[0].y + bv0.x, c[1].y + bv0.y, c[2].y + bv0.z, c[3].y + bv0.w};
        float4 hi1 = {c[4].y + bv1.x, c[5].y + bv1.y, c[6].y + bv1.z, c[7].y + bv1.w};
        *(float4*)&C[r0] = lo0;
        *(float4*)&C[r0 + 4] = hi0;
        *(float4*)&C[r0 + N3] = lo1;
        *(float4*)&C[r0 + N3 + 4] = hi1;
    }
}

// ---------------- zero hidden state ----------------------------------------
__global__ void zero_h_kernel() {
    int i = blockIdx.x * blockDim.x + threadIdx.x;
    if (i < 2 * 32 * 1024) g_h[i] = 0.f;
}

// ---------------- persistent GRU recurrence --------------------------------
// Per-warp cp.async double-buffered h staging + f32x2 FMAs (round-4 proven).
// NEW: distributed-flag grid barrier (no same-address atomics, no per-thread
// threadfence). Each CTA release-stores its 128B-strided flag; CTA 0 polls all
// flags with G threads + __syncthreads_and, then release-stores g_gen; others
// acquire-poll g_gen. Targets are absolute monotonic (base + t + 1) so stale
// flag values always compare smaller — deterministic across layers/replays.
template<int K, int HC>
__global__ __launch_bounds__(256) void recur_kernel(
    const float* __restrict__ xg, const float* __restrict__ w_hh,
    const float* __restrict__ b_hh, float* __restrict__ out,
    long os_b, long os_t, long os_j)
{
    constexpr int NR = 3 * HC;
    constexpr int H = K;
    constexpr int k4n = (K / 4) / 8;          // float4 k-groups per warp
    constexpr int CW = 8;                     // k-groups per chunk
    constexpr int NC = k4n / CW;              // chunks per warp
    extern __shared__ __align__(16) float smem[];
    float* w_s = smem;                                   // [NR][K]
    float4* hb4 = (float4*)(smem + NR * K);              // [8 warps][2 bufs][CW*32] float4
    float* red = smem + NR * K + 8 * 2 * CW * 32 * 4;    // [8][NR][32]
    __shared__ unsigned sbase;

    int tid = threadIdx.x;
    int cta = blockIdx.x;
    int G = gridDim.x;
    int j0 = cta * HC;

    for (int r = 0; r < NR; ++r) {
        int gate = r / HC, jl = r % HC;
        int j = j0 + jl;
        for (int k = tid * 4; k < K; k += 1024) {
            float4 v = make_float4(0.f, 0.f, 0.f, 0.f);
            if (j < H) v = *(const float4*)&w_hh[(size_t)(gate * H + j) * K + k];
            *(float4*)&w_s[r * K + k] = v;
        }
    }
    if (tid == 0) sbase = *(volatile unsigned*)&g_gen;
    __syncthreads();
    unsigned base = sbase;

    int warp = tid >> 5, lane = tid & 31;
    int k4b = warp * k4n;
    float4* mybuf = hb4 + warp * 2 * CW * 32;
    const float* wcol0 = w_s + k4b * 4;

    int ejl = tid >> 5, eb = tid & 31;
    int jg = j0 + ejl;
    bool epi = (tid < HC * 32) && (jg < H);
    int hidx = (jg >> 2) * 128 + eb * 4 + (jg & 3);
    const float* xgbase = xg + (size_t)eb * TT * (3 * H) + jg;
    float bh0 = 0.f, bh1 = 0.f, bh2 = 0.f;
    if (epi) { bh0 = b_hh[jg]; bh1 = b_hh[H + jg]; bh2 = b_hh[2 * H + jg]; }
    float hreg = 0.f;

    for (int t = 0; t < TT; ++t) {
        int p = t & 1;
        const float4* hp = (const float4*)&g_h[p * 32 * 1024] + (size_t)k4b * 32;

#pragma unroll
        for (int c0 = 0; c0 < 2 && c0 < NC; ++c0) {
            float4* dst = mybuf + c0 * CW * 32;
            const float4* src = hp + c0 * CW * 32;
#pragma unroll
            for (int kk = 0; kk < CW; ++kk)
                cpa16(dst + kk * 32 + lane, src + kk * 32 + lane);
            asm volatile("cp.async.commit_group;" ::: "memory");
        }

        float xr = 0.f, xz = 0.f, xn = 0.f;
        if (epi) {
            const float* xp = xgbase + (size_t)t * (3 * H);
            xr = __ldcs(xp); xz = __ldcs(xp + H); xn = __ldcs(xp + 2 * H);
        }

        unsigned long long acc[NR];
#pragma unroll
        for (int r = 0; r < NR; ++r) acc[r] = 0ull;

#pragma unroll
        for (int c = 0; c < NC; ++c) {
            if (c + 1 < NC) asm volatile("cp.async.wait_group 1;" ::: "memory");
            else            asm volatile("cp.async.wait_group 0;" ::: "memory");
            const float4* buf = mybuf + (c & 1) * CW * 32;
            const float* wc = wcol0 + c * CW * 4;
#pragma unroll
            for (int kk = 0; kk < CW; ++kk) {
                HU hv; hv.f = buf[kk * 32 + lane];
#pragma unroll
                for (int r = 0; r < NR; ++r) {
                    ulonglong2 wv = *(const ulonglong2*)&wc[r * K + kk * 4];
                    fma2(acc[r], hv.u.x, wv.x);
                    fma2(acc[r], hv.u.y, wv.y);
                }
            }
            if (c + 2 < NC) {
                float4* dst = mybuf + (c & 1) * CW * 32;
                const float4* src = hp + (c + 2) * CW * 32;
#pragma unroll
                for (int kk = 0; kk < CW; ++kk)
                    cpa16(dst + kk * 32 + lane, src + kk * 32 + lane);
                asm volatile("cp.async.commit_group;" ::: "memory");
            }
        }

#pragma unroll
        for (int r = 0; r < NR; ++r) {
            float2 f = up2(acc[r]);
            red[(warp * NR + r) * 32 + lane] = f.x + f.y;
        }
        __syncthreads();

        if (epi) {
            float s[3];
#pragma unroll
            for (int gate = 0; gate < 3; ++gate) {
                float v = (gate == 0) ? bh0 : (gate == 1) ? bh1 : bh2;
#pragma unroll
                for (int w = 0; w < 8; ++w)
                    v += red[(w * NR + gate * HC + ejl) * 32 + eb];
                s[gate] = v;
            }
            float r_ = 1.f / (1.f + __expf(-(xr + s[0])));
            float z_ = 1.f / (1.f + __expf(-(xz + s[1])));
            float n_ = tanhf(xn + r_ * s[2]);
            float hnew = (1.f - z_) * n_ + z_ * hreg;
            hreg = hnew;
            g_h[(p ^ 1) * 32 * 1024 + hidx] = hnew;
            __stcs(&out[(size_t)eb * os_b + (size_t)t * os_t + (size_t)jg * os_j], hnew);
        }

        // ---- distributed-flag grid barrier ----
        __syncthreads();   // all epilogue h stores done (CTA scope)
        unsigned target = base + t + 1;
        if (cta == 0) {
            // poll every CTA's flag (thread tid watches flag[tid]); own CTA
            // needs no flag — syncthreads above covers it.
            int ok = (tid == 0 || tid >= G) ? 1
                   : ((int)(ld_acq(&g_flag[tid * 32]) - target) >= 0);
            while (!__syncthreads_and(ok)) {
                ok = (tid == 0 || tid >= G) ? 1
                   : ((int)(ld_acq(&g_flag[tid * 32]) - target) >= 0);
            }
            if (tid == 0) st_rel(&g_gen, target);
        } else {
            if (tid == 0) {
                st_rel(&g_flag[cta * 32], target);
                while ((int)(ld_acq(&g_gen) - target) < 0) { }
            }
            __syncthreads();
        }
    }
}

extern "C" void kernel_launch(void* const* d_in, const int* in_sizes, int n_in,
                              void* d_out, int out_size) {
    const float* x = (const float*)d_in[0];
    const float* wih[4]; const float* whh[4]; const float* bih[4]; const float* bhh[4];
    for (int l = 0; l < 4; ++l) {
        wih[l] = (const float*)d_in[1 + 4 * l];
        whh[l] = (const float*)d_in[2 + 4 * l];
        bih[l] = (const float*)d_in[3 + 4 * l];
        bhh[l] = (const float*)d_in[4 + 4 * l];
    }
    float *xg, *a0, *a1;
    cudaGetSymbolAddress((void**)&xg, g_xg);
    cudaGetSymbolAddress((void**)&a0, g_act0);
    cudaGetSymbolAddress((void**)&a1, g_act1);
    float* dout = (float*)d_out;

    const int SMEM4 = (3 * 4 * 512) * 4 + 65536 + (8 * 12 * 32) * 4;    // 102400 B
    const int SMEM7 = (3 * 7 * 1024) * 4 + 65536 + (8 * 21 * 32) * 4;   // 173056 B
    cudaFuncSetAttribute(recur_kernel<512, 4>, cudaFuncAttributeMaxDynamicSharedMemorySize, SMEM4);
    cudaFuncSetAttribute(recur_kernel<1024, 7>, cudaFuncAttributeMaxDynamicSharedMemorySize, SMEM7);

    struct Cfg { const float* A; int K; int H; long sb, st, sk; float* out; long ob, ot, oj; };
    Cfg cfg[4] = {
        { x,   256,  512, (long)256 * 2048,  1,    2048, a0,   (long)2048 * 512,  512,  1    },
        { a0,  512,  512, (long)2048 * 512,  512,  1,    a1,   (long)2048 * 512,  512,  1    },
        { a1,  512, 1024, (long)2048 * 512,  512,  1,    a0,   (long)2048 * 1024, 1024, 1    },
        { a0, 1024, 1024, (long)2048 * 1024, 1024, 1,    dout, (long)1024 * 2048, 1,    2048 },
    };

    for (int l = 0; l < 4; ++l) {
        int N3 = 3 * cfg[l].H;
        dim3 gg(N3 / 128, (BB * TT) / 128);
        gemm_xg<<<gg, 256>>>(cfg[l].A, wih[l], bih[l], xg,
                             cfg[l].K, N3, cfg[l].sb, cfg[l].st, cfg[l].sk);
        zero_h_kernel<<<64, 1024>>>();
        if (cfg[l].H == 512)
            recur_kernel<512, 4><<<128, 256, SMEM4>>>(xg, whh[l], bhh[l], cfg[l].out,
                                                      cfg[l].ob, cfg[l].ot, cfg[l].oj);
        else
            recur_kernel<1024, 7><<<147, 256, SMEM7>>>(xg, whh[l], bhh[l], cfg[l].out,
                                                       cfg[l].ob, cfg[l].ot, cfg[l].oj);
    }
}

// round 7
// speedup vs baseline: 1.1132x; 1.1132x over previous
#include <cuda_runtime.h>
#include <cstdint>

// Problem constants
constexpr int BB = 32;       // batch
constexpr int TT = 2048;     // time steps

// ---------------- scratch (static device globals; no allocation allowed) ----
__device__ float g_xg[(size_t)BB * TT * 3072];     // input-gate projections, max 3H=3072
__device__ float g_act0[(size_t)BB * TT * 1024];   // activations ping  [b][j][t]
__device__ float g_act1[(size_t)BB * TT * 1024];   // activations pong  [b][j][t]
__device__ float g_wT[1024 * 3072];                // transposed w_ih   [K][3H]
__device__ float g_h[2 * 32 * 1024];               // hidden state, double buffered, f4[k>>2][b][k&3]
__device__ unsigned g_sub[4 * 64];                 // tree barrier: 4 sub-counters, 256B-strided
__device__ unsigned g_root;                        // tree barrier: root counter
__device__ unsigned g_gen;                         // tree barrier: generation (release target)

// ---------------- packed f32x2 helpers (sm_100+) ---------------------------
__device__ __forceinline__ void fma2(unsigned long long& a, unsigned long long x, unsigned long long y) {
    asm("fma.rn.f32x2 %0, %1, %2, %0;" : "+l"(a) : "l"(x), "l"(y));
}
__device__ __forceinline__ unsigned long long pk2(float x, float y) {
    unsigned long long r; asm("mov.b64 %0, {%1,%2};" : "=l"(r) : "f"(x), "f"(y)); return r;
}
__device__ __forceinline__ float2 up2(unsigned long long v) {
    float2 f; asm("mov.b64 {%0,%1}, %2;" : "=f"(f.x), "=f"(f.y) : "l"(v)); return f;
}

union HU { float4 f; ulonglong2 u; };

__device__ __forceinline__ void cpa16(void* dst, const void* src) {
    uint32_t d = (uint32_t)__cvta_generic_to_shared(dst);
    asm volatile("cp.async.cg.shared.global [%0], [%1], 16;" :: "r"(d), "l"(src));
}

__device__ __forceinline__ void st_rel(unsigned* p, unsigned v) {
    asm volatile("st.release.gpu.global.u32 [%0], %1;" :: "l"(p), "r"(v) : "memory");
}
__device__ __forceinline__ unsigned ld_acq(const unsigned* p) {
    unsigned v;
    asm volatile("ld.acquire.gpu.global.u32 %0, [%1];" : "=r"(v) : "l"(p) : "memory");
    return v;
}
__device__ __forceinline__ unsigned atom_add_rel(unsigned* p, unsigned v) {
    unsigned old;
    asm volatile("atom.release.gpu.global.add.u32 %0, [%1], %2;"
                 : "=r"(old) : "l"(p), "r"(v) : "memory");
    return old;
}

// ---------------- one-shot weight transpose: Wt[k][n] = W[n][k] -------------
__global__ void transpose_w(const float* __restrict__ W, float* __restrict__ Wt,
                            int K, int N3)
{
    __shared__ float tile[32][33];
    int kb = blockIdx.x * 32, nb = blockIdx.y * 32;
    for (int r = threadIdx.y; r < 32; r += 8)
        tile[r][threadIdx.x] = W[(size_t)(nb + r) * K + kb + threadIdx.x];
    __syncthreads();
    for (int r = threadIdx.y; r < 32; r += 8)
        Wt[(size_t)(kb + r) * N3 + nb + threadIdx.x] = tile[threadIdx.x][r];
}

// ---------------- input projection GEMM -------------------------------------
// C[m, n] = sum_k A[m, k] * Wt[k, n] + bias[n],  m = b*TT + t
// A layout: [b][k][t] (t contiguous): elem = A + b*sb + k*TT + t.
// Wt layout: [K][N3] (n contiguous).
// BM=128, BN=128, BK=16; 256 threads; 8x8/thread; 3-stage cp.async pipeline
// (2 K-blocks always in flight; no exposed global latency).
__global__ __launch_bounds__(256, 2) void gemm_xg(
    const float* __restrict__ A, const float* __restrict__ Wt,
    const float* __restrict__ bias, float* __restrict__ C,
    int K, int N3, long sb)
{
    extern __shared__ __align__(16) float dsm[];
    float* As = dsm;                    // [3][16][128]
    float* Bs = dsm + 3 * 16 * 128;     // [3][16][128]

    int tid = threadIdx.x;
    int n0 = blockIdx.x * 128;
    int m0 = blockIdx.y * 128;
    int bidx = m0 / TT;
    int t0 = m0 % TT;                   // TT % 128 == 0: tile within one batch row
    const float* Ab = A + (size_t)bidx * sb + t0;
    int tx = tid & 15, ty = tid >> 4;

    unsigned long long acc[4][8];
#pragma unroll
    for (int p = 0; p < 4; ++p)
#pragma unroll
        for (int j = 0; j < 8; ++j) acc[p][j] = 0ull;

    auto issue = [&](int s, int k0) {
#pragma unroll
        for (int i = 0; i < 2; ++i) {
            int lin = tid + i * 256;
            int k = lin >> 5, q4 = (lin & 31) * 4;
            cpa16(&As[(s * 16 + k) * 128 + q4], Ab + q4 + (size_t)(k0 + k) * TT);
            cpa16(&Bs[(s * 16 + k) * 128 + q4], &Wt[(size_t)(k0 + k) * N3 + n0 + q4]);
        }
    };

    issue(0, 0);  asm volatile("cp.async.commit_group;" ::: "memory");
    issue(1, 16); asm volatile("cp.async.commit_group;" ::: "memory");

    int s = 0;
    for (int k0 = 0; k0 < K; k0 += 16) {
        asm volatile("cp.async.wait_group 1;" ::: "memory");
        __syncthreads();
        // stage k0+32 into buffer (s+2)%3 (its previous contents were consumed
        // at the prior iteration — the syncthreads above proves everyone's done)
        if (k0 + 32 < K) issue((s + 2) % 3, k0 + 32);
        asm volatile("cp.async.commit_group;" ::: "memory");   // possibly empty; keeps count invariant

        const float* Ak = &As[s * 16 * 128];
        const float* Bk = &Bs[s * 16 * 128];
#pragma unroll
        for (int k = 0; k < 16; ++k) {
            const ulonglong2* ap = (const ulonglong2*)&Ak[k * 128 + ty * 8];
            ulonglong2 A0 = ap[0], A1 = ap[1];
            unsigned long long am[4] = {A0.x, A0.y, A1.x, A1.y};
            float4 b0 = *(const float4*)&Bk[k * 128 + tx * 8];
            float4 b1 = *(const float4*)&Bk[k * 128 + tx * 8 + 4];
            unsigned long long bd[8] = {pk2(b0.x, b0.x), pk2(b0.y, b0.y),
                                        pk2(b0.z, b0.z), pk2(b0.w, b0.w),
                                        pk2(b1.x, b1.x), pk2(b1.y, b1.y),
                                        pk2(b1.z, b1.z), pk2(b1.w, b1.w)};
#pragma unroll
            for (int p = 0; p < 4; ++p)
#pragma unroll
                for (int j = 0; j < 8; ++j) fma2(acc[p][j], am[p], bd[j]);
        }
        s = (s == 2) ? 0 : s + 1;
    }

    float4 bv0 = *(const float4*)&bias[n0 + tx * 8];
    float4 bv1 = *(const float4*)&bias[n0 + tx * 8 + 4];
#pragma unroll
    for (int p = 0; p < 4; ++p) {
        float2 c[8];
#pragma unroll
        for (int j = 0; j < 8; ++j) c[j] = up2(acc[p][j]);
        size_t r0 = (size_t)(m0 + ty * 8 + 2 * p) * N3 + n0 + tx * 8;
        float4 lo0 = {c[0].x + bv0.x, c[1].x + bv0.y, c[2].x + bv0.z, c[3].x + bv0.w};
        float4 hi0 = {c[4].x + bv1.x, c[5].x + bv1.y, c[6].x + bv1.z, c[7].x + bv1.w};
        float4 lo1 = {c[0].y + bv0.x, c[1].y + bv0.y, c[2].y + bv0.z, c[3].y + bv0.w};
        float4 hi1 = {c[4].y + bv1.x, c[5].y + bv1.y, c[6].y + bv1.z, c[7].y + bv1.w};
        *(float4*)&C[r0] = lo0;
        *(float4*)&C[r0 + 4] = hi0;
        *(float4*)&C[r0 + N3] = lo1;
        *(float4*)&C[r0 + N3 + 4] = hi1;
    }
}

// ---------------- zero hidden state + barrier counters ----------------------
__global__ void zero_h_kernel() {
    int i = blockIdx.x * blockDim.x + threadIdx.x;
    if (i < 2 * 32 * 1024) g_h[i] = 0.f;
    if (i < 4 * 64) g_sub[i] = 0u;
    if (i == 0) { g_root = 0u; g_gen = 0u; }
}

// ---------------- persistent GRU recurrence --------------------------------
// Round-4 proven core (per-warp cp.async double-buffered h staging + f32x2
// FMAs). NEW: tree grid barrier — arrivals spread over 4 sub-counters
// (release atomics), sub-last arrives at root, root-last release-stores g_gen;
// all others acquire-poll g_gen. Counters zeroed per launch (stream-ordered),
// so targets are exact: sub_i reaches n_i*(t+1), root reaches 4*(t+1).
// Output written as [b][j][t] (t contiguous) so the next GEMM can cp.async.
template<int K, int HC>
__global__ __launch_bounds__(256) void recur_kernel(
    const float* __restrict__ xg, const float* __restrict__ w_hh,
    const float* __restrict__ b_hh, float* __restrict__ out,
    long os_b)
{
    constexpr int NR = 3 * HC;
    constexpr int H = K;
    constexpr int k4n = (K / 4) / 8;          // float4 k-groups per warp
    constexpr int CW = 8;                     // k-groups per chunk
    constexpr int NC = k4n / CW;              // chunks per warp
    extern __shared__ __align__(16) float smem[];
    float* w_s = smem;                                   // [NR][K]
    float4* hb4 = (float4*)(smem + NR * K);              // [8 warps][2 bufs][CW*32] float4
    float* red = smem + NR * K + 8 * 2 * CW * 32 * 4;    // [8][NR][32]

    int tid = threadIdx.x;
    int cta = blockIdx.x;
    int G = gridDim.x;
    int j0 = cta * HC;

    for (int r = 0; r < NR; ++r) {
        int gate = r / HC, jl = r % HC;
        int j = j0 + jl;
        for (int k = tid * 4; k < K; k += 1024) {
            float4 v = make_float4(0.f, 0.f, 0.f, 0.f);
            if (j < H) v = *(const float4*)&w_hh[(size_t)(gate * H + j) * K + k];
            *(float4*)&w_s[r * K + k] = v;
        }
    }
    __syncthreads();

    int warp = tid >> 5, lane = tid & 31;
    int k4b = warp * k4n;
    float4* mybuf = hb4 + warp * 2 * CW * 32;
    const float* wcol0 = w_s + k4b * 4;

    int ejl = tid >> 5, eb = tid & 31;
    int jg = j0 + ejl;
    bool epi = (tid < HC * 32) && (jg < H);
    int hidx = (jg >> 2) * 128 + eb * 4 + (jg & 3);
    const float* xgbase = xg + (size_t)eb * TT * (3 * H) + jg;
    float bh0 = 0.f, bh1 = 0.f, bh2 = 0.f;
    if (epi) { bh0 = b_hh[jg]; bh1 = b_hh[H + jg]; bh2 = b_hh[2 * H + jg]; }
    float hreg = 0.f;

    // barrier constants for this CTA
    int sub = cta & 3;
    unsigned nsub = (unsigned)(G >> 2) + ((G & 3) > sub ? 1u : 0u);

    for (int t = 0; t < TT; ++t) {
        int p = t & 1;
        const float4* hp = (const float4*)&g_h[p * 32 * 1024] + (size_t)k4b * 32;

#pragma unroll
        for (int c0 = 0; c0 < 2 && c0 < NC; ++c0) {
            float4* dst = mybuf + c0 * CW * 32;
            const float4* src = hp + c0 * CW * 32;
#pragma unroll
            for (int kk = 0; kk < CW; ++kk)
                cpa16(dst + kk * 32 + lane, src + kk * 32 + lane);
            asm volatile("cp.async.commit_group;" ::: "memory");
        }

        float xr = 0.f, xz = 0.f, xn = 0.f;
        if (epi) {
            const float* xp = xgbase + (size_t)t * (3 * H);
            xr = __ldcs(xp); xz = __ldcs(xp + H); xn = __ldcs(xp + 2 * H);
        }

        unsigned long long acc[NR];
#pragma unroll
        for (int r = 0; r < NR; ++r) acc[r] = 0ull;

#pragma unroll
        for (int c = 0; c < NC; ++c) {
            if (c + 1 < NC) asm volatile("cp.async.wait_group 1;" ::: "memory");
            else            asm volatile("cp.async.wait_group 0;" ::: "memory");
            const float4* buf = mybuf + (c & 1) * CW * 32;
            const float* wc = wcol0 + c * CW * 4;
#pragma unroll
            for (int kk = 0; kk < CW; ++kk) {
                HU hv; hv.f = buf[kk * 32 + lane];
#pragma unroll
                for (int r = 0; r < NR; ++r) {
                    ulonglong2 wv = *(const ulonglong2*)&wc[r * K + kk * 4];
                    fma2(acc[r], hv.u.x, wv.x);
                    fma2(acc[r], hv.u.y, wv.y);
                }
            }
            if (c + 2 < NC) {
                float4* dst = mybuf + (c & 1) * CW * 32;
                const float4* src = hp + (c + 2) * CW * 32;
#pragma unroll
                for (int kk = 0; kk < CW; ++kk)
                    cpa16(dst + kk * 32 + lane, src + kk * 32 + lane);
                asm volatile("cp.async.commit_group;" ::: "memory");
            }
        }

#pragma unroll
        for (int r = 0; r < NR; ++r) {
            float2 f = up2(acc[r]);
            red[(warp * NR + r) * 32 + lane] = f.x + f.y;
        }
        __syncthreads();

        if (epi) {
            float s[3];
#pragma unroll
            for (int gate = 0; gate < 3; ++gate) {
                float v = (gate == 0) ? bh0 : (gate == 1) ? bh1 : bh2;
#pragma unroll
                for (int w = 0; w < 8; ++w)
                    v += red[(w * NR + gate * HC + ejl) * 32 + eb];
                s[gate] = v;
            }
            float r_ = 1.f / (1.f + __expf(-(xr + s[0])));
            float z_ = 1.f / (1.f + __expf(-(xz + s[1])));
            float n_ = tanhf(xn + r_ * s[2]);
            float hnew = (1.f - z_) * n_ + z_ * hreg;
            hreg = hnew;
            g_h[(p ^ 1) * 32 * 1024 + hidx] = hnew;
            // out[b][j][t]: t contiguous for the next GEMM's cp.async
            __stcs(&out[(size_t)eb * os_b + (size_t)jg * TT + t], hnew);
        }

        // ---- tree grid barrier ----
        __syncthreads();   // epilogue h stores happen-before tid0's release atomic
        if (tid == 0) {
            unsigned tstep = (unsigned)(t + 1);
            unsigned old = atom_add_rel(&g_sub[sub * 64], 1u);
            bool rootlast = false;
            if (old + 1u == nsub * tstep) {                 // last arrival in this sub-group
                unsigned ro = atom_add_rel(&g_root, 1u);
                if (ro + 1u == 4u * tstep) {                // last sub-group overall
                    st_rel(&g_gen, tstep);
                    rootlast = true;
                }
            }
            if (!rootlast)
                while ((int)(ld_acq(&g_gen) - tstep) < 0) { }
        }
        __syncthreads();
    }
}

extern "C" void kernel_launch(void* const* d_in, const int* in_sizes, int n_in,
                              void* d_out, int out_size) {
    const float* x = (const float*)d_in[0];
    const float* wih[4]; const float* whh[4]; const float* bih[4]; const float* bhh[4];
    for (int l = 0; l < 4; ++l) {
        wih[l] = (const float*)d_in[1 + 4 * l];
        whh[l] = (const float*)d_in[2 + 4 * l];
        bih[l] = (const float*)d_in[3 + 4 * l];
        bhh[l] = (const float*)d_in[4 + 4 * l];
    }
    float *xg, *a0, *a1, *wT;
    cudaGetSymbolAddress((void**)&xg, g_xg);
    cudaGetSymbolAddress((void**)&a0, g_act0);
    cudaGetSymbolAddress((void**)&a1, g_act1);
    cudaGetSymbolAddress((void**)&wT, g_wT);
    float* dout = (float*)d_out;

    const int SMEMG = 3 * 16 * 128 * 4 * 2;                             // 49152 B
    const int SMEM4 = (3 * 4 * 512) * 4 + 65536 + (8 * 12 * 32) * 4;    // 102400 B
    const int SMEM7 = (3 * 7 * 1024) * 4 + 65536 + (8 * 21 * 32) * 4;   // 173056 B
    cudaFuncSetAttribute(gemm_xg, cudaFuncAttributeMaxDynamicSharedMemorySize, SMEMG);
    cudaFuncSetAttribute(recur_kernel<512, 4>, cudaFuncAttributeMaxDynamicSharedMemorySize, SMEM4);
    cudaFuncSetAttribute(recur_kernel<1024, 7>, cudaFuncAttributeMaxDynamicSharedMemorySize, SMEM7);

    // A layout is [b][k][t] (t contiguous) for every layer.
    struct Cfg { const float* A; int K; int H; long sb; float* out; };
    Cfg cfg[4] = {
        { x,   256,  512, (long)256 * 2048,  a0   },
        { a0,  512,  512, (long)512 * 2048,  a1   },
        { a1,  512, 1024, (long)512 * 2048,  a0   },
        { a0, 1024, 1024, (long)1024 * 2048, dout },
    };

    for (int l = 0; l < 4; ++l) {
        int K = cfg[l].K, H = cfg[l].H, N3 = 3 * H;
        transpose_w<<<dim3(K / 32, N3 / 32), dim3(32, 8)>>>(wih[l], wT, K, N3);
        dim3 gg(N3 / 128, (BB * TT) / 128);
        gemm_xg<<<gg, 256, SMEMG>>>(cfg[l].A, wT, bih[l], xg, K, N3, cfg[l].sb);
        zero_h_kernel<<<64, 1024>>>();
        long ob = (long)H * TT;
        if (H == 512)
            recur_kernel<512, 4><<<128, 256, SMEM4>>>(xg, whh[l], bhh[l], cfg[l].out, ob);
        else
            recur_kernel<1024, 7><<<147, 256, SMEM7>>>(xg, whh[l], bhh[l], cfg[l].out, ob);
    }
}

// round 10
// speedup vs baseline: 1.1135x; 1.0003x over previous
#include <cuda_runtime.h>
#include <cstdint>

constexpr int BB = 32;       // batch (== warp width, lane = b)
constexpr int TT = 2048;     // time steps
constexpr int NSTEPS = TT + 6;
constexpr int GRID = 148;    // 4 * 37 exactly

// ---------------- scratch (static device globals) ---------------------------
__device__ float g_xg[(size_t)BB * TT * 1536];   // L0 input projections [b*TT+t][1536]
__device__ float g_wT[256 * 1536];               // L0 w_ih transposed [K][3H]
__device__ float g_hr[8 * 32 * 1024];            // h rings [layer 0..3][par] f4[k>>2][b][k&3]
__device__ float g_xr[6 * 3072 * 32];            // xg rings [layer-1][par][row][b]
__device__ unsigned g_sub[4 * 64];               // tree barrier sub-counters (256B-strided)
__device__ unsigned g_root;
__device__ unsigned g_gen;

// ---------------- packed f32x2 helpers --------------------------------------
__device__ __forceinline__ void fma2(unsigned long long& a, unsigned long long x, unsigned long long y) {
    asm("fma.rn.f32x2 %0, %1, %2, %0;" : "+l"(a) : "l"(x), "l"(y));
}
__device__ __forceinline__ unsigned long long pk2(float x, float y) {
    unsigned long long r; asm("mov.b64 %0, {%1,%2};" : "=l"(r) : "f"(x), "f"(y)); return r;
}
__device__ __forceinline__ float2 up2(unsigned long long v) {
    float2 f; asm("mov.b64 {%0,%1}, %2;" : "=f"(f.x), "=f"(f.y) : "l"(v)); return f;
}
union HU { float4 f; ulonglong2 u; };

__device__ __forceinline__ void cpa16(void* dst, const void* src) {
    uint32_t d = (uint32_t)__cvta_generic_to_shared(dst);
    asm volatile("cp.async.cg.shared.global [%0], [%1], 16;" :: "r"(d), "l"(src));
}
__device__ __forceinline__ void st_rel(unsigned* p, unsigned v) {
    asm volatile("st.release.gpu.global.u32 [%0], %1;" :: "l"(p), "r"(v) : "memory");
}
__device__ __forceinline__ unsigned ld_acq(const unsigned* p) {
    unsigned v;
    asm volatile("ld.acquire.gpu.global.u32 %0, [%1];" : "=r"(v) : "l"(p) : "memory");
    return v;
}
__device__ __forceinline__ unsigned atom_add_ar(unsigned* p, unsigned v) {
    unsigned old;
    asm volatile("atom.acq_rel.gpu.global.add.u32 %0, [%1], %2;"
                 : "=r"(old) : "l"(p), "r"(v) : "memory");
    return old;
}

// ---------------- tree grid barrier -----------------------------------------
__device__ __forceinline__ void grid_barrier(int tid, int cta, unsigned tstep) {
    __syncthreads();
    if (tid == 0) {
        int sub = cta & 3;
        unsigned old = atom_add_ar(&g_sub[sub * 64], 1u);
        bool rootlast = false;
        if (old + 1u == 37u * tstep) {
            unsigned ro = atom_add_ar(&g_root, 1u);
            if (ro + 1u == 4u * tstep) { st_rel(&g_gen, tstep); rootlast = true; }
        }
        if (!rootlast)
            while ((int)(ld_acq(&g_gen) - tstep) < 0) { }
    }
    __syncthreads();
}

// ---------------- one-shot weight transpose: Wt[k][n] = W[n][k] -------------
__global__ void transpose_w(const float* __restrict__ W, float* __restrict__ Wt,
                            int K, int N3)
{
    __shared__ float tile[32][33];
    int kb = blockIdx.x * 32, nb = blockIdx.y * 32;
    for (int r = threadIdx.y; r < 32; r += 8)
        tile[r][threadIdx.x] = W[(size_t)(nb + r) * K + kb + threadIdx.x];
    __syncthreads();
    for (int r = threadIdx.y; r < 32; r += 8)
        Wt[(size_t)(kb + r) * N3 + nb + threadIdx.x] = tile[threadIdx.x][r];
}

// ---------------- bulk L0 input-projection GEMM (round-7 proven) ------------
// Adds b_ih[n] + (n < 2H ? b_hh[n] : 0) — the r/z parts of b_hh are pre-folded.
__global__ __launch_bounds__(256, 2) void gemm_xg(
    const float* __restrict__ A, const float* __restrict__ Wt,
    const float* __restrict__ bih, const float* __restrict__ bhh,
    float* __restrict__ C, int K, int N3, int H, long sb)
{
    extern __shared__ __align__(16) float dsm[];
    float* As = dsm;                    // [3][16][128]
    float* Bs = dsm + 3 * 16 * 128;     // [3][16][128]

    int tid = threadIdx.x;
    int n0 = blockIdx.x * 128;
    int m0 = blockIdx.y * 128;
    int bidx = m0 / TT;
    int t0 = m0 % TT;
    const float* Ab = A + (size_t)bidx * sb + t0;
    int tx = tid & 15, ty = tid >> 4;

    unsigned long long acc[4][8];
#pragma unroll
    for (int p = 0; p < 4; ++p)
#pragma unroll
        for (int j = 0; j < 8; ++j) acc[p][j] = 0ull;

    auto issue = [&](int s, int k0) {
#pragma unroll
        for (int i = 0; i < 2; ++i) {
            int lin = tid + i * 256;
            int k = lin >> 5, q4 = (lin & 31) * 4;
            cpa16(&As[(s * 16 + k) * 128 + q4], Ab + q4 + (size_t)(k0 + k) * TT);
            cpa16(&Bs[(s * 16 + k) * 128 + q4], &Wt[(size_t)(k0 + k) * N3 + n0 + q4]);
        }
    };

    issue(0, 0);  asm volatile("cp.async.commit_group;" ::: "memory");
    issue(1, 16); asm volatile("cp.async.commit_group;" ::: "memory");

    int s = 0;
#pragma unroll 1
    for (int k0 = 0; k0 < K; k0 += 16) {
        asm volatile("cp.async.wait_group 1;" ::: "memory");
        __syncthreads();
        if (k0 + 32 < K) issue((s + 2) % 3, k0 + 32);
        asm volatile("cp.async.commit_group;" ::: "memory");

        const float* Ak = &As[s * 16 * 128];
        const float* Bk = &Bs[s * 16 * 128];
#pragma unroll
        for (int k = 0; k < 16; ++k) {
            const ulonglong2* ap = (const ulonglong2*)&Ak[k * 128 + ty * 8];
            ulonglong2 A0 = ap[0], A1 = ap[1];
            unsigned long long am[4] = {A0.x, A0.y, A1.x, A1.y};
            float4 b0 = *(const float4*)&Bk[k * 128 + tx * 8];
            float4 b1 = *(const float4*)&Bk[k * 128 + tx * 8 + 4];
            unsigned long long bd[8] = {pk2(b0.x, b0.x), pk2(b0.y, b0.y),
                                        pk2(b0.z, b0.z), pk2(b0.w, b0.w),
                                        pk2(b1.x, b1.x), pk2(b1.y, b1.y),
                                        pk2(b1.z, b1.z), pk2(b1.w, b1.w)};
#pragma unroll
            for (int p = 0; p < 4; ++p)
#pragma unroll
                for (int j = 0; j < 8; ++j) fma2(acc[p][j], am[p], bd[j]);
        }
        s = (s == 2) ? 0 : s + 1;
    }

    float bias[8];
#pragma unroll
    for (int j = 0; j < 8; ++j) {
        int n = n0 + tx * 8 + j;
        bias[j] = bih[n] + (n < 2 * H ? bhh[n] : 0.f);
    }
#pragma unroll
    for (int p = 0; p < 4; ++p) {
        float2 c[8];
#pragma unroll
        for (int j = 0; j < 8; ++j) c[j] = up2(acc[p][j]);
        size_t r0 = (size_t)(m0 + ty * 8 + 2 * p) * N3 + n0 + tx * 8;
        float4 lo0 = {c[0].x + bias[0], c[1].x + bias[1], c[2].x + bias[2], c[3].x + bias[3]};
        float4 hi0 = {c[4].x + bias[4], c[5].x + bias[5], c[6].x + bias[6], c[7].x + bias[7]};
        float4 lo1 = {c[0].y + bias[0], c[1].y + bias[1], c[2].y + bias[2], c[3].y + bias[3]};
        float4 hi1 = {c[4].y + bias[4], c[5].y + bias[5], c[6].y + bias[6], c[7].y + bias[7]};
        *(float4*)&C[r0] = lo0;
        *(float4*)&C[r0 + 4] = hi0;
        *(float4*)&C[r0 + N3] = lo1;
        *(float4*)&C[r0 + N3 + 4] = hi1;
    }
}

// ---------------- zero rings + barrier counters -----------------------------
__global__ void zero_misc() {
    int i = blockIdx.x * blockDim.x + threadIdx.x;
    int stride = gridDim.x * blockDim.x;
    for (int k = i; k < 8 * 32 * 1024; k += stride) g_hr[k] = 0.f;
    for (int k = i; k < 6 * 3072 * 32; k += stride) g_xr[k] = 0.f;
    if (i < 256) g_sub[i] = 0u;
    if (i == 0) { g_root = 0u; g_gen = 0u; }
}

// ============================================================================
// Wavefront tasks. Per global step s:
//   recur layer l : t = s - 2l         (h ring read slot s&1, write slot (s&1)^1;
//                                       xg ring read slot (s&1)^1 for l>=1)
//   xproj layer l : t = s - (2l-1)     (h ring (l-1) read slot s&1; xg write slot s&1)
// Weights streamed from L2 per step via 4-stage cp.async chunks of 32 k.
// Chunk loops and step loops are kept rolled (#pragma unroll 1) — full
// unrolling made the cubin explode and killed compilation (round 8).
// FINAL layer writes BOTH the h ring (needed for its own next-step matvec)
// and dout — omitting the ring write was the round-9 correctness bug.
// ============================================================================

// ---------------- recurrence task -------------------------------------------
template<int K, int UPW, int CUS, int LAYER, bool FINAL>
__device__ void run_recur(int cl, const float* __restrict__ whh,
                          const float* __restrict__ bhh,
                          const float* __restrict__ xg0, float* __restrict__ dout,
                          int tid, int cta, float* smem)
{
    constexpr int H = K;
    constexpr int CUP = UPW * 8;              // padded units per CTA
    constexpr int RS = 3 * CUP;               // staged W rows per chunk
    constexpr int NCH = K / 32;               // chunks per step
    constexpr int WG = RS * 8;                // W granules per chunk
    constexpr int TG = WG + 256;              // + h granules
    constexpr int GI = (TG + 255) / 256;

    float* wb = smem;                          // [4][RS][32]
    float* hb = smem + 4 * RS * 32;            // [4][8][128]

    int warp = tid >> 5, lane = tid & 31;
    int ub = cl * CUS;
    int w0 = warp * UPW;

    bool uact[UPW]; int uidx[UPW]; float bhn[UPW]; float hreg[UPW];
#pragma unroll
    for (int uu = 0; uu < UPW; ++uu) {
        int ul = w0 + uu;
        int u = ub + ul;
        bool act = (ul < CUS) && (u < H);
        uact[uu] = act;
        uidx[uu] = act ? u : (H - 1);
        bhn[uu] = bhh[2 * H + uidx[uu]];
        hreg[uu] = 0.f;
    }

#pragma unroll 1
    for (int s = 0; s < NSTEPS; ++s) {
        int t = s - 2 * LAYER;
        bool active = (t >= 0) && (t < TT);
        if (active) {
            const float* hr_r = g_hr + (size_t)(LAYER * 2 + (s & 1)) * (32 * 1024);

            // prefetch xg for this step (consumed at epilogue, ~20K cyc later)
            float xrv[UPW], xzv[UPW], xnv[UPW];
            if (LAYER == 0) {
                const float* xp = xg0 + ((size_t)lane * TT + t) * 1536;
#pragma unroll
                for (int uu = 0; uu < UPW; ++uu) {
                    int u = uidx[uu];
                    xrv[uu] = __ldcs(xp + u);
                    xzv[uu] = __ldcs(xp + 512 + u);
                    xnv[uu] = __ldcs(xp + 1024 + u);
                }
            } else {
                const float* xp = g_xr + (size_t)((LAYER - 1) * 2 + ((s & 1) ^ 1)) * (3072 * 32);
#pragma unroll
                for (int uu = 0; uu < UPW; ++uu) {
                    int u = uidx[uu];
                    xrv[uu] = __ldcg(xp + (size_t)u * 32 + lane);
                    xzv[uu] = __ldcg(xp + (size_t)(H + u) * 32 + lane);
                    xnv[uu] = __ldcg(xp + (size_t)(2 * H + u) * 32 + lane);
                }
            }

            auto stage = [&](int c) {
                int st = c & 3;
                int k0 = c * 32;
#pragma unroll
                for (int i = 0; i < GI; ++i) {
                    int idx = tid + i * 256;
                    if (idx < WG) {
                        int r = idx >> 3, g8 = idx & 7;
                        int gate = r / CUP, ul = r % CUP;
                        int u = ub + ul; if (u >= H) u = H - 1;
                        cpa16(&wb[(st * RS + r) * 32 + g8 * 4],
                              whh + (size_t)(gate * H + u) * K + k0 + g8 * 4);
                    } else if (idx < TG) {
                        int j = idx - WG;
                        int k4 = j >> 5, b = j & 31;
                        cpa16(&hb[(st * 8 + k4) * 128 + b * 4],
                              hr_r + (size_t)((k0 >> 2) + k4) * 128 + b * 4);
                    }
                }
                asm volatile("cp.async.commit_group;" ::: "memory");
            };
            stage(0); stage(1); stage(2);

            unsigned long long acc[3][UPW];
#pragma unroll
            for (int g = 0; g < 3; ++g)
#pragma unroll
                for (int uu = 0; uu < UPW; ++uu) acc[g][uu] = 0ull;

#pragma unroll 1
            for (int c = 0; c < NCH; ++c) {
                asm volatile("cp.async.wait_group 2;" ::: "memory");
                __syncthreads();           // chunk c landed everywhere; chunk c-1 consumed
                if (c + 3 < NCH) stage(c + 3);
                else asm volatile("cp.async.commit_group;" ::: "memory");
                int st = c & 3;
                const float* wcs = &wb[st * RS * 32];
                const float* hcs = &hb[st * 8 * 128];
#pragma unroll
                for (int k4 = 0; k4 < 8; ++k4) {
                    HU hv; hv.f = *(const float4*)&hcs[k4 * 128 + lane * 4];
#pragma unroll
                    for (int g = 0; g < 3; ++g)
#pragma unroll
                        for (int uu = 0; uu < UPW; ++uu) {
                            int r = g * CUP + w0 + uu;
                            ulonglong2 wv = *(const ulonglong2*)&wcs[r * 32 + k4 * 4];
                            fma2(acc[g][uu], hv.u.x, wv.x);
                            fma2(acc[g][uu], hv.u.y, wv.y);
                        }
                }
            }

            float* hr_w = g_hr + (size_t)(LAYER * 2 + ((s & 1) ^ 1)) * (32 * 1024);
#pragma unroll
            for (int uu = 0; uu < UPW; ++uu) {
                if (!uact[uu]) continue;
                int u = uidx[uu];
                float2 fr = up2(acc[0][uu]); float sr = fr.x + fr.y;
                float2 fz = up2(acc[1][uu]); float sz = fz.x + fz.y;
                float2 fn = up2(acc[2][uu]); float sn = fn.x + fn.y;
                float r_ = 1.f / (1.f + __expf(-(xrv[uu] + sr)));   // b_hh_r pre-folded into xg
                float z_ = 1.f / (1.f + __expf(-(xzv[uu] + sz)));   // b_hh_z pre-folded into xg
                float n_ = tanhf(xnv[uu] + r_ * (sn + bhn[uu]));
                float hnew = (1.f - z_) * n_ + z_ * hreg[uu];
                hreg[uu] = hnew;
                hr_w[(u >> 2) * 128 + lane * 4 + (u & 3)] = hnew;   // ALWAYS: own next step needs it
                if (FINAL)
                    __stcs(&dout[(size_t)lane * 1024 * TT + (size_t)u * TT + t], hnew);
            }
        }
        grid_barrier(tid, cta, (unsigned)(s + 1));
    }
}

// ---------------- input-projection task (layers 1..3) ------------------------
template<int K, int HOUT, int RPW, int RPC, int LAYER>
__device__ void run_xproj(int cl, const float* __restrict__ wih,
                          const float* __restrict__ bih, const float* __restrict__ bhh,
                          int tid, int cta, float* smem)
{
    constexpr int N3 = 3 * HOUT;
    constexpr int RSP = RPW * 8;
    constexpr int NCH = K / 32;
    constexpr int WG = RSP * 8;
    constexpr int TG = WG + 256;
    constexpr int GI = (TG + 255) / 256;

    float* wb = smem;                          // [4][RSP][32]
    float* hb = smem + 4 * RSP * 32;           // [4][8][128]

    int warp = tid >> 5, lane = tid & 31;
    int rb = cl * RPC;
    int r0w = warp * RPW;

    bool ract[RPW]; int ridx[RPW]; float biasr[RPW];
#pragma unroll
    for (int rr = 0; rr < RPW; ++rr) {
        int rl = r0w + rr;
        int row = rb + rl;
        bool act = (rl < RPC) && (row < N3);
        ract[rr] = act;
        ridx[rr] = act ? row : (N3 - 1);
        biasr[rr] = bih[ridx[rr]] + (ridx[rr] < 2 * HOUT ? bhh[ridx[rr]] : 0.f);
    }

#pragma unroll 1
    for (int s = 0; s < NSTEPS; ++s) {
        int t = s - (2 * LAYER - 1);
        bool active = (t >= 0) && (t < TT);
        if (active) {
            const float* hr_r = g_hr + (size_t)((LAYER - 1) * 2 + (s & 1)) * (32 * 1024);
            float* xw = g_xr + (size_t)((LAYER - 1) * 2 + (s & 1)) * (3072 * 32);

            auto stage = [&](int c) {
                int st = c & 3;
                int k0 = c * 32;
#pragma unroll
                for (int i = 0; i < GI; ++i) {
                    int idx = tid + i * 256;
                    if (idx < WG) {
                        int r = idx >> 3, g8 = idx & 7;
                        int row = rb + r; if (row >= N3) row = N3 - 1;
                        cpa16(&wb[(st * RSP + r) * 32 + g8 * 4],
                              wih + (size_t)row * K + k0 + g8 * 4);
                    } else if (idx < TG) {
                        int j = idx - WG;
                        int k4 = j >> 5, b = j & 31;
                        cpa16(&hb[(st * 8 + k4) * 128 + b * 4],
                              hr_r + (size_t)((k0 >> 2) + k4) * 128 + b * 4);
                    }
                }
                asm volatile("cp.async.commit_group;" ::: "memory");
            };
            stage(0); stage(1); stage(2);

            unsigned long long acc[RPW];
#pragma unroll
            for (int rr = 0; rr < RPW; ++rr) acc[rr] = 0ull;

#pragma unroll 1
            for (int c = 0; c < NCH; ++c) {
                asm volatile("cp.async.wait_group 2;" ::: "memory");
                __syncthreads();
                if (c + 3 < NCH) stage(c + 3);
                else asm volatile("cp.async.commit_group;" ::: "memory");
                int st = c & 3;
                const float* wcs = &wb[st * RSP * 32];
                const float* hcs = &hb[st * 8 * 128];
#pragma unroll
                for (int k4 = 0; k4 < 8; ++k4) {
                    HU hv; hv.f = *(const float4*)&hcs[k4 * 128 + lane * 4];
#pragma unroll
                    for (int rr = 0; rr < RPW; ++rr) {
                        ulonglong2 wv = *(const ulonglong2*)&wcs[(r0w + rr) * 32 + k4 * 4];
                        fma2(acc[rr], hv.u.x, wv.x);
                        fma2(acc[rr], hv.u.y, wv.y);
                    }
                }
            }

#pragma unroll
            for (int rr = 0; rr < RPW; ++rr) {
                if (!ract[rr]) continue;
                float2 f = up2(acc[rr]);
                xw[(size_t)ridx[rr] * 32 + lane] = f.x + f.y + biasr[rr];
            }
        }
        grid_barrier(tid, cta, (unsigned)(s + 1));
    }
}

// ---------------- mega kernel: all tasks, one launch -------------------------
__global__ __launch_bounds__(256, 1) void mega(
    float* __restrict__ dout,
    const float* whh0, const float* bhh0,
    const float* wih1, const float* bih1, const float* whh1, const float* bhh1,
    const float* wih2, const float* bih2, const float* whh2, const float* bhh2,
    const float* wih3, const float* bih3, const float* whh3, const float* bhh3)
{
    extern __shared__ __align__(16) float smem[];
    int tid = threadIdx.x, cta = blockIdx.x;
    if      (cta <   9) run_recur< 512, 8, 57, 0, false>(cta,       whh0, bhh0, g_xg, nullptr, tid, cta, smem);
    else if (cta <  18) run_xproj< 512,  512, 22, 171, 1>(cta -   9, wih1, bih1, bhh1, tid, cta, smem);
    else if (cta <  27) run_recur< 512, 8, 57, 1, false>(cta -  18, whh1, bhh1, nullptr, nullptr, tid, cta, smem);
    else if (cta <  44) run_xproj< 512, 1024, 23, 181, 2>(cta -  27, wih2, bih2, bhh2, tid, cta, smem);
    else if (cta <  79) run_recur<1024, 4, 30, 2, false>(cta -  44, whh2, bhh2, nullptr, nullptr, tid, cta, smem);
    else if (cta < 113) run_xproj<1024, 1024, 12,  91, 3>(cta -  79, wih3, bih3, bhh3, tid, cta, smem);
    else                run_recur<1024, 4, 30, 3, true >(cta - 113, whh3, bhh3, nullptr, dout, tid, cta, smem);
}

extern "C" void kernel_launch(void* const* d_in, const int* in_sizes, int n_in,
                              void* d_out, int out_size) {
    const float* x = (const float*)d_in[0];
    const float* wih[4]; const float* whh[4]; const float* bih[4]; const float* bhh[4];
    for (int l = 0; l < 4; ++l) {
        wih[l] = (const float*)d_in[1 + 4 * l];
        whh[l] = (const float*)d_in[2 + 4 * l];
        bih[l] = (const float*)d_in[3 + 4 * l];
        bhh[l] = (const float*)d_in[4 + 4 * l];
    }
    float *xg, *wT;
    cudaGetSymbolAddress((void**)&xg, g_xg);
    cudaGetSymbolAddress((void**)&wT, g_wT);
    float* dout = (float*)d_out;

    const int SMEMG = 3 * 16 * 128 * 4 * 2;                     // 49152 B
    const int SMEMM = (4 * 192 * 32 + 4 * 8 * 128) * 4;         // 114688 B (max task)
    cudaFuncSetAttribute(gemm_xg, cudaFuncAttributeMaxDynamicSharedMemorySize, SMEMG);
    cudaFuncSetAttribute(mega, cudaFuncAttributeMaxDynamicSharedMemorySize, SMEMM);

    // L0 bulk input projection: x is [B][256][T] (t contiguous)
    transpose_w<<<dim3(256 / 32, 1536 / 32), dim3(32, 8)>>>(wih[0], wT, 256, 1536);
    gemm_xg<<<dim3(1536 / 128, (BB * TT) / 128), 256, SMEMG>>>(
        x, wT, bih[0], bhh[0], xg, 256, 1536, 512, (long)256 * 2048);
    zero_misc<<<512, 256>>>();
    mega<<<GRID, 256, SMEMM>>>(
        dout,
        whh[0], bhh[0],
        wih[1], bih[1], whh[1], bhh[1],
        wih[2], bih[2], whh[2], bhh[2],
        wih[3], bih[3], whh[3], bhh[3]);
}